// round 9
// baseline (speedup 1.0000x reference)
#include <cuda_runtime.h>
#include <cstdint>

#define BATCH 256
#define L 4096
#define H 128

// h1 trajectory scratch: [batch][t][H]  (512 MB, static device global — allowed)
__device__ float g_h1[(size_t)BATCH * L * H];

// ---------- packed f32x2 helpers ----------
__device__ __forceinline__ uint64_t pack2f(float a, float b) {
    uint64_t r; asm("mov.b64 %0, {%1, %2};" : "=l"(r) : "f"(a), "f"(b)); return r;
}
__device__ __forceinline__ float hsum2(uint64_t v) {
    float a, b; asm("mov.b64 {%0, %1}, %2;" : "=f"(a), "=f"(b) : "l"(v)); return a + b;
}
__device__ __forceinline__ uint64_t ffma2(uint64_t a, uint64_t b, uint64_t c) {
    uint64_t d; asm("fma.rn.f32x2 %0, %1, %2, %3;" : "=l"(d) : "l"(a), "l"(b), "l"(c)); return d;
}
__device__ __forceinline__ uint64_t fadd2(uint64_t a, uint64_t b) {
    uint64_t d; asm("add.rn.f32x2 %0, %1, %2;" : "=l"(d) : "l"(a), "l"(b)); return d;
}
__device__ __forceinline__ float elu1(float x) {
    return fmaxf(x, 0.f) + (__expf(fminf(x, 0.f)) - 1.f);
}
__device__ __forceinline__ uint32_t smem_u32(const void* p) {
    return (uint32_t)__cvta_generic_to_shared(p);
}

// ============================================================================
// Phase 1: layer-1 scan. One CTA = one batch element, 256 threads = (i, s):
// i = tid>>1 hidden unit, s = tid&1 k-half. 64 weight floats/thread -> occ 2.
// Writes h1(t) to g_h1.
// ============================================================================
__global__ void __launch_bounds__(256, 2)
rnn_l1_kernel(const int* __restrict__ x,
              const float* __restrict__ W_in,
              const float* __restrict__ W_c)
{
    __shared__ __align__(16) float sh_h[2][H];
    __shared__ float sh_r[3 * H];
    __shared__ uint8_t sh_x[L];

    const int tid = threadIdx.x;
    const int i   = tid >> 1;
    const int s   = tid & 1;
    const int b   = blockIdx.x;

    const int* xg = x + (size_t)b * L;
    #pragma unroll 4
    for (int idx = tid; idx < L; idx += 256) sh_x[idx] = (uint8_t)xg[idx];
    if (tid < 2 * H) sh_r[tid] = elu1(W_in[tid]);
    if (tid < H)     { sh_r[2 * H + tid] = 0.f; sh_h[0][tid] = 0.f; }

    // layer-1 weights, k-half s (64 floats = 32 packed regs)
    uint64_t w[32];
    #pragma unroll
    for (int j = 0; j < 16; ++j) {
        const int k0 = 8 * j + 4 * s;
        w[2*j]   = pack2f(W_c[(k0+0)*H + i], W_c[(k0+1)*H + i]);
        w[2*j+1] = pack2f(W_c[(k0+2)*H + i], W_c[(k0+3)*H + i]);
    }
    float* g = g_h1 + (size_t)b * L * H;
    __syncthreads();

    for (int t = 0; t < L; ++t) {
        const int p = t & 1;
        const float* hr = &sh_h[p][0];
        const int   prev = t ? (int)sh_x[t - 1] : 2;
        const float rv   = sh_r[prev * H + i];

        uint64_t a0 = 0, a1 = 0, a2 = 0, a3 = 0;
        #pragma unroll
        for (int j = 0; j < 16; j += 2) {
            const int o = 8 * j + 4 * s;
            const ulonglong2 h0 = *(const ulonglong2*)(hr + o);
            const ulonglong2 h1 = *(const ulonglong2*)(hr + o + 8);
            a0 = ffma2(w[2*j],   h0.x, a0);
            a1 = ffma2(w[2*j+1], h0.y, a1);
            a2 = ffma2(w[2*j+2], h1.x, a2);
            a3 = ffma2(w[2*j+3], h1.y, a3);
        }
        float d = hsum2(fadd2(fadd2(a0, a2), fadd2(a1, a3)));
        d += __shfl_xor_sync(0xffffffffu, d, 1);

        const float h1n = elu1(d) + rv;
        if (s == 0) sh_h[p ^ 1][i] = h1n;      // recurrence state
        else        g[(size_t)t * H + i] = h1n; // trajectory to gmem (coalesced)

        __syncthreads();
    }
}

// ============================================================================
// Phase 2: layer-2 scan + log-prob head. Streams h1 via 8-slot cp.async ring
// (depth-4 pipelining). Same (i, s) layout, occ 2.
// ============================================================================
__global__ void __launch_bounds__(256, 2)
rnn_l2_kernel(const int* __restrict__ x,
              const float* __restrict__ W_c,
              const float* __restrict__ W_out,
              const float* __restrict__ b_out,
              float* __restrict__ out)
{
    __shared__ __align__(16) float sh_h[2][H];       // h2 ping-pong
    __shared__ __align__(16) float sh_ring[8][H];    // h1 prefetch ring (4 KB)
    __shared__ __align__(16) float sh_prod[32][H];   // head ring (16 KB)
    __shared__ uint8_t sh_x[L];
    __shared__ float sh_acc[8];

    const int tid  = threadIdx.x;
    const int warp = tid >> 5;
    const int lane = tid & 31;
    const int i    = tid >> 1;
    const int s    = tid & 1;
    const int b    = blockIdx.x;

    const int* xg = x + (size_t)b * L;
    #pragma unroll 4
    for (int idx = tid; idx < L; idx += 256) sh_x[idx] = (uint8_t)xg[idx];
    if (tid < H) sh_h[0][tid] = 0.f;

    // layer-2 weights, k-half s
    const float* Wc1 = W_c + H * H;
    uint64_t w[32];
    #pragma unroll
    for (int j = 0; j < 16; ++j) {
        const int k0 = 8 * j + 4 * s;
        w[2*j]   = pack2f(Wc1[(k0+0)*H + i], Wc1[(k0+1)*H + i]);
        w[2*j+1] = pack2f(Wc1[(k0+2)*H + i], Wc1[(k0+3)*H + i]);
    }
    const float wout_i = W_out[i];
    const float bout   = b_out[0];
    const float* g = g_h1 + (size_t)b * L * H;

    // prime cp.async ring: slots 0..3 <- h1(0..3)  (s==0 threads own element i)
    if (s == 0) {
        #pragma unroll
        for (int d = 0; d < 4; ++d) {
            const uint32_t dst = smem_u32(&sh_ring[d][i]);
            asm volatile("cp.async.ca.shared.global [%0], [%1], 4;"
                         :: "r"(dst), "l"(g + (size_t)d * H + i));
            asm volatile("cp.async.commit_group;");
        }
    }
    __syncthreads();

    float acc = 0.f;
    for (int t = 0; t < L; ++t) {
        if (s == 0) asm volatile("cp.async.wait_group 3;");
        __syncthreads();   // single barrier/step: ring data + prior h2/prod stores

        const int p = t & 1;
        const float* hr = &sh_h[p][0];
        const float h1v = sh_ring[t & 7][i];

        uint64_t a0 = 0, a1 = 0, a2 = 0, a3 = 0;
        #pragma unroll
        for (int j = 0; j < 16; j += 2) {
            const int o = 8 * j + 4 * s;
            const ulonglong2 h0 = *(const ulonglong2*)(hr + o);
            const ulonglong2 h1 = *(const ulonglong2*)(hr + o + 8);
            a0 = ffma2(w[2*j],   h0.x, a0);
            a1 = ffma2(w[2*j+1], h0.y, a1);
            a2 = ffma2(w[2*j+2], h1.x, a2);
            a3 = ffma2(w[2*j+3], h1.y, a3);
        }
        float d = hsum2(fadd2(fadd2(a0, a2), fadd2(a1, a3)));
        d += __shfl_xor_sync(0xffffffffu, d, 1);

        const float h2n = elu1(d) + h1v;
        if (s == 0) sh_h[p ^ 1][i] = h2n;
        else        sh_prod[t & 31][i] = h2n * wout_i;

        // prefetch h1(t+4) into slot (t+4)&7 (distinct from slot t&7)
        if (s == 0) {
            if (t + 4 < L) {
                const uint32_t dst = smem_u32(&sh_ring[(t + 4) & 7][i]);
                asm volatile("cp.async.ca.shared.global [%0], [%1], 4;"
                             :: "r"(dst), "l"(g + (size_t)(t + 4) * H + i));
            }
            asm volatile("cp.async.commit_group;");
        }

        // amortized head: window [t-16, t-1], 2 slots per warp
        if ((t & 15) == 0 && t > 0) {
            #pragma unroll
            for (int e = 0; e < 2; ++e) {
                const int u = t - 16 + 2 * warp + e;
                const float4 v = *(const float4*)&sh_prod[u & 31][lane * 4];
                float sr = (v.x + v.y) + (v.z + v.w);
                #pragma unroll
                for (int off = 16; off; off >>= 1)
                    sr += __shfl_xor_sync(0xffffffffu, sr, off);
                if (lane == 0) {
                    const float logit = sr + bout;
                    const int   xt    = sh_x[u];
                    const float m     = fmaxf(logit, 0.f);
                    const float lse   = m + __logf(__expf(-m) + __expf(logit - m));
                    acc += 0.5f * ((xt ? logit : 0.f) - lse);
                }
            }
        }
    }

    __syncthreads();
    // epilogue: last 16 slots [L-16, L-1], 2 per warp
    #pragma unroll
    for (int e = 0; e < 2; ++e) {
        const int u = L - 16 + 2 * warp + e;
        const float4 v = *(const float4*)&sh_prod[u & 31][lane * 4];
        float sr = (v.x + v.y) + (v.z + v.w);
        #pragma unroll
        for (int off = 16; off; off >>= 1)
            sr += __shfl_xor_sync(0xffffffffu, sr, off);
        if (lane == 0) {
            const float logit = sr + bout;
            const int   xt    = sh_x[u];
            const float m     = fmaxf(logit, 0.f);
            const float lse   = m + __logf(__expf(-m) + __expf(logit - m));
            acc += 0.5f * ((xt ? logit : 0.f) - lse);
        }
    }

    if (lane == 0) sh_acc[warp] = acc;
    __syncthreads();
    if (tid == 0) {
        float a = 0.f;
        #pragma unroll
        for (int wq = 0; wq < 8; ++wq) a += sh_acc[wq];
        out[b] = a;
    }
}

extern "C" void kernel_launch(void* const* d_in, const int* in_sizes, int n_in,
                              void* d_out, int out_size)
{
    const int*   x     = (const int*)  d_in[0];
    const float* W_in  = (const float*)d_in[1];
    const float* W_c   = (const float*)d_in[2];
    const float* W_out = (const float*)d_in[3];
    const float* b_out = (const float*)d_in[4];

    rnn_l1_kernel<<<BATCH, 256>>>(x, W_in, W_c);
    rnn_l2_kernel<<<BATCH, 256>>>(x, W_c, W_out, b_out, (float*)d_out);
}

// round 10
// speedup vs baseline: 1.1039x; 1.1039x over previous
#include <cuda_runtime.h>
#include <cstdint>

#define BATCH 256
#define L 4096
#define H 128
#define NPAIR (BATCH / 2)   // 128 producer CTAs + 128 consumer CTAs

// h1 trajectory scratch (512 MB) + producer progress counters
__device__ float        g_h1[(size_t)BATCH * L * H];
__device__ unsigned int g_prog[NPAIR];

// ---------- packed f32x2 helpers ----------
__device__ __forceinline__ uint64_t pack2f(float a, float b) {
    uint64_t r; asm("mov.b64 %0, {%1, %2};" : "=l"(r) : "f"(a), "f"(b)); return r;
}
__device__ __forceinline__ float hsum2(uint64_t v) {
    float a, b; asm("mov.b64 {%0, %1}, %2;" : "=f"(a), "=f"(b) : "l"(v)); return a + b;
}
__device__ __forceinline__ uint64_t ffma2(uint64_t a, uint64_t b, uint64_t c) {
    uint64_t d; asm("fma.rn.f32x2 %0, %1, %2, %3;" : "=l"(d) : "l"(a), "l"(b), "l"(c)); return d;
}
__device__ __forceinline__ uint64_t fadd2(uint64_t a, uint64_t b) {
    uint64_t d; asm("add.rn.f32x2 %0, %1, %2;" : "=l"(d) : "l"(a), "l"(b)); return d;
}
__device__ __forceinline__ float elu1(float x) {
    return fmaxf(x, 0.f) + (__expf(fminf(x, 0.f)) - 1.f);
}
__device__ __forceinline__ uint32_t smem_u32(const void* p) {
    return (uint32_t)__cvta_generic_to_shared(p);
}
__device__ __forceinline__ unsigned ld_acquire(const unsigned* p) {
    unsigned v; asm volatile("ld.acquire.gpu.u32 %0, [%1];" : "=r"(v) : "l"(p)); return v;
}

__global__ void rnn_init_kernel() {
    if (threadIdx.x < NPAIR) g_prog[threadIdx.x] = 0u;
}

// ============================================================================
// Producer (blocks 0..127): layer-1 scan for batches {2k, 2k+1}.
// Thread (i = tid>>1, s = tid&1): k-half of W_c[0] columns in regs (64 regs),
// computes half-dots for BOTH batches (4 FMA chains), shfl_xor(1) combine,
// finalizes batch s, stores h1 to SMEM ping-pong AND to g_h1 (coalesced).
// Publishes g_prog[k] = t+1 every 8 steps (barrier + fence + atomicExch).
// ============================================================================
__device__ void producer_fn(int k, const int* __restrict__ x,
                            const float* __restrict__ W_in,
                            const float* __restrict__ W_c)
{
    __shared__ __align__(16) float sh_h[2][2 * H];
    __shared__ float sh_r[3 * H];
    __shared__ uint8_t sh_x[2 * L];

    const int tid = threadIdx.x;
    const int i   = tid >> 1;
    const int s   = tid & 1;
    const int b0  = 2 * k;

    const int* xg = x + (size_t)b0 * L;
    #pragma unroll 4
    for (int idx = tid; idx < 2 * L; idx += 256) sh_x[idx] = (uint8_t)xg[idx];
    if (tid < 2 * H) sh_r[tid] = elu1(W_in[tid]);
    if (tid < H)     sh_r[2 * H + tid] = 0.f;
    if (tid < 2 * H) sh_h[0][tid] = 0.f;

    uint64_t w[32];
    #pragma unroll
    for (int j = 0; j < 16; ++j) {
        const int k0 = 8 * j + 4 * s;
        w[2*j]   = pack2f(W_c[(k0+0)*H + i], W_c[(k0+1)*H + i]);
        w[2*j+1] = pack2f(W_c[(k0+2)*H + i], W_c[(k0+3)*H + i]);
    }
    float* g = g_h1 + (size_t)k * 2 * L * H;
    __syncthreads();

    for (int t = 0; t < L; ++t) {
        const int p = t & 1;
        const float* hr = &sh_h[p][0];
        const int   prev = t ? (int)sh_x[s * L + t - 1] : 2;
        const float rv   = sh_r[prev * H + i];

        uint64_t a00 = 0, a01 = 0, a10 = 0, a11 = 0;
        #pragma unroll
        for (int j = 0; j < 16; ++j) {
            const int o = 8 * j + 4 * s;
            const ulonglong2 h0 = *(const ulonglong2*)(hr + o);
            const ulonglong2 h1 = *(const ulonglong2*)(hr + H + o);
            a00 = ffma2(w[2*j],   h0.x, a00);
            a01 = ffma2(w[2*j+1], h0.y, a01);
            a10 = ffma2(w[2*j],   h1.x, a10);
            a11 = ffma2(w[2*j+1], h1.y, a11);
        }
        float p0 = hsum2(fadd2(a00, a01));
        float p1 = hsum2(fadd2(a10, a11));
        p0 += __shfl_xor_sync(0xffffffffu, p0, 1);
        p1 += __shfl_xor_sync(0xffffffffu, p1, 1);

        const float h1n = elu1(s ? p1 : p0) + rv;
        sh_h[p ^ 1][s * H + i] = h1n;
        g[(size_t)t * 2 * H + s * H + i] = h1n;

        __syncthreads();
        if ((t & 7) == 7 && tid == 0) {
            __threadfence();
            atomicExch(&g_prog[k], (unsigned)(t + 1));
        }
    }
}

// ============================================================================
// Consumer (blocks 128..255): layer-2 scan + log-prob head for batches {2k,2k+1}.
// Streams h1 via 8-slot cp.async ring (depth 4), gated on g_prog[k].
// Head amortized: 16-slot prod ring, every 8 steps each warp reduces 1 slot
// for both batches. One __syncthreads per step.
// ============================================================================
__device__ void consumer_fn(int k, const int* __restrict__ x,
                            const float* __restrict__ W_c,
                            const float* __restrict__ W_out,
                            const float* __restrict__ b_out,
                            float* __restrict__ out)
{
    __shared__ __align__(16) float sh_h[2][2 * H];        // h2 ping-pong (2 KB)
    __shared__ __align__(16) float sh_ring[8][2 * H];     // h1 prefetch ring (8 KB)
    __shared__ __align__(16) float sh_prod[16][2 * H];    // head ring (16 KB)
    __shared__ uint8_t sh_x[2 * L];                       // 8 KB
    __shared__ float sh_acc[8][2];

    const int tid  = threadIdx.x;
    const int warp = tid >> 5;
    const int lane = tid & 31;
    const int i    = tid >> 1;
    const int s    = tid & 1;
    const int b0   = 2 * k;

    const int* xg = x + (size_t)b0 * L;
    #pragma unroll 4
    for (int idx = tid; idx < 2 * L; idx += 256) sh_x[idx] = (uint8_t)xg[idx];
    if (tid < 2 * H) sh_h[0][tid] = 0.f;

    const float* Wc1 = W_c + H * H;
    uint64_t w[32];
    #pragma unroll
    for (int j = 0; j < 16; ++j) {
        const int k0 = 8 * j + 4 * s;
        w[2*j]   = pack2f(Wc1[(k0+0)*H + i], Wc1[(k0+1)*H + i]);
        w[2*j+1] = pack2f(Wc1[(k0+2)*H + i], Wc1[(k0+3)*H + i]);
    }
    const float wout_i = W_out[i];
    const float bout   = b_out[0];
    const float* g = g_h1 + (size_t)k * 2 * L * H;

    // ---- wait for first 4 steps, prime the ring ----
    unsigned avail = ld_acquire(&g_prog[k]);
    while (avail < 4u) avail = ld_acquire(&g_prog[k]);
    if (s == 0) {
        #pragma unroll
        for (int d = 0; d < 4; ++d) {
            const uint32_t dst = smem_u32(&sh_ring[d][2 * i]);
            asm volatile("cp.async.ca.shared.global [%0], [%1], 8;"
                         :: "r"(dst), "l"(g + (size_t)d * 2 * H + 2 * i));
            asm volatile("cp.async.commit_group;");
        }
    }
    __syncthreads();

    float hacc0 = 0.f, hacc1 = 0.f;
    for (int t = 0; t < L; ++t) {
        // gate the upcoming prefetch of h1(t+4)
        if (t + 4 < L) {
            const unsigned need = (unsigned)(t + 5);
            while (avail < need) avail = ld_acquire(&g_prog[k]);
        }
        if (s == 0) asm volatile("cp.async.wait_group 3;");
        __syncthreads();   // ring slot t&7 valid + prior h2/prod stores visible

        const int p = t & 1;
        const float* hr = &sh_h[p][0];
        const float h1v = sh_ring[t & 7][s * H + i];

        uint64_t a00 = 0, a01 = 0, a10 = 0, a11 = 0;
        #pragma unroll
        for (int j = 0; j < 16; ++j) {
            const int o = 8 * j + 4 * s;
            const ulonglong2 h0 = *(const ulonglong2*)(hr + o);
            const ulonglong2 h1 = *(const ulonglong2*)(hr + H + o);
            a00 = ffma2(w[2*j],   h0.x, a00);
            a01 = ffma2(w[2*j+1], h0.y, a01);
            a10 = ffma2(w[2*j],   h1.x, a10);
            a11 = ffma2(w[2*j+1], h1.y, a11);
        }
        float p0 = hsum2(fadd2(a00, a01));
        float p1 = hsum2(fadd2(a10, a11));
        p0 += __shfl_xor_sync(0xffffffffu, p0, 1);
        p1 += __shfl_xor_sync(0xffffffffu, p1, 1);

        const float h2n = elu1(s ? p1 : p0) + h1v;
        sh_h[p ^ 1][s * H + i] = h2n;
        sh_prod[t & 15][s * H + i] = h2n * wout_i;

        // prefetch h1(t+4) into slot (t+4)&7
        if (s == 0) {
            if (t + 4 < L) {
                const uint32_t dst = smem_u32(&sh_ring[(t + 4) & 7][2 * i]);
                asm volatile("cp.async.ca.shared.global [%0], [%1], 8;"
                             :: "r"(dst), "l"(g + (size_t)(t + 4) * 2 * H + 2 * i));
            }
            asm volatile("cp.async.commit_group;");
        }

        // amortized head: window [t-8, t-1], 1 slot/warp, both batches
        if ((t & 7) == 0 && t > 0) {
            const int u = t - 8 + warp;
            #pragma unroll
            for (int b = 0; b < 2; ++b) {
                const float4 v = *(const float4*)&sh_prod[u & 15][b * H + lane * 4];
                float sr = (v.x + v.y) + (v.z + v.w);
                #pragma unroll
                for (int off = 16; off; off >>= 1)
                    sr += __shfl_xor_sync(0xffffffffu, sr, off);
                if (lane == 0) {
                    const float logit = sr + bout;
                    const int   xt    = sh_x[b * L + u];
                    const float m     = fmaxf(logit, 0.f);
                    const float lse   = m + __logf(__expf(-m) + __expf(logit - m));
                    const float gv    = 0.5f * ((xt ? logit : 0.f) - lse);
                    if (b == 0) hacc0 += gv; else hacc1 += gv;
                }
            }
        }
    }

    __syncthreads();
    // epilogue: last 8 slots [L-8, L-1]
    {
        const int u = L - 8 + warp;
        #pragma unroll
        for (int b = 0; b < 2; ++b) {
            const float4 v = *(const float4*)&sh_prod[u & 15][b * H + lane * 4];
            float sr = (v.x + v.y) + (v.z + v.w);
            #pragma unroll
            for (int off = 16; off; off >>= 1)
                sr += __shfl_xor_sync(0xffffffffu, sr, off);
            if (lane == 0) {
                const float logit = sr + bout;
                const int   xt    = sh_x[b * L + u];
                const float m     = fmaxf(logit, 0.f);
                const float lse   = m + __logf(__expf(-m) + __expf(logit - m));
                const float gv    = 0.5f * ((xt ? logit : 0.f) - lse);
                if (b == 0) hacc0 += gv; else hacc1 += gv;
            }
        }
    }

    if (lane == 0) { sh_acc[warp][0] = hacc0; sh_acc[warp][1] = hacc1; }
    __syncthreads();
    if (tid < 2) {
        float a = 0.f;
        #pragma unroll
        for (int wq = 0; wq < 8; ++wq) a += sh_acc[wq][tid];
        out[b0 + tid] = a;
    }
}

__global__ void __launch_bounds__(256, 2)
rnn_pipe_kernel(const int* __restrict__ x,
                const float* __restrict__ W_in,
                const float* __restrict__ W_c,
                const float* __restrict__ W_out,
                const float* __restrict__ b_out,
                float* __restrict__ out)
{
    if (blockIdx.x < NPAIR)
        producer_fn(blockIdx.x, x, W_in, W_c);
    else
        consumer_fn(blockIdx.x - NPAIR, x, W_c, W_out, b_out, out);
}

extern "C" void kernel_launch(void* const* d_in, const int* in_sizes, int n_in,
                              void* d_out, int out_size)
{
    const int*   x     = (const int*)  d_in[0];
    const float* W_in  = (const float*)d_in[1];
    const float* W_c   = (const float*)d_in[2];
    const float* W_out = (const float*)d_in[3];
    const float* b_out = (const float*)d_in[4];

    rnn_init_kernel<<<1, 128>>>();
    rnn_pipe_kernel<<<2 * NPAIR, 256>>>(x, W_in, W_c, W_out, b_out, (float*)d_out);
}